// round 11
// baseline (speedup 1.0000x reference)
#include <cuda_runtime.h>
#include <cuda_fp16.h>

#define CDIM 128
#define HDIM 64
#define EDIM 16
#define N_MAX 50000
#define E_MAX 810000

// Packed fp32x2 helpers (sm_100a: fma.rn.f32x2, PTX ISA 8.6)
#define PACK2(out, lo, hi) \
    asm("mov.b64 %0, {%1, %2};" : "=l"(out) \
        : "r"(__float_as_uint(lo)), "r"(__float_as_uint(hi)))
#define UNPACK2(lo, hi, in) \
    asm("mov.b64 {%0, %1}, %2;" : "=r"(lo), "=r"(hi) : "l"(in))
#define FMA2(d, a, b, c) \
    asm("fma.rn.f32x2 %0, %1, %2, %3;" : "=l"(d) : "l"(a), "l"(b), "l"(c))

// Node-level precompute (float4 layout, 16 float4 per node row):
//  g_s4[n*16+q] = (h@W1^T + att_b)[n][4q..4q+3]
//  g_t4[n*16+q] = (h@W2^T)[n][4q..4q+3]
//  g_h4[n*16+q] = (x@fc_w^T + fc_b)[n][4q..4q+3]
// Edge-level precompute:
//  g_r2[e*32+p] = half2{r[2p], r[2p+1]},  r = edge_attr@W3^T (fp16 storage)
//  g_eidx[e]    = {src, dst} int32, clamped to [0,N)
__device__ float4  g_s4[N_MAX * 16];
__device__ float4  g_t4[N_MAX * 16];
__device__ float4  g_h4[N_MAX * 16];
__device__ __half2 g_r2[(size_t)E_MAX * 32];
__device__ int2    g_eidx[E_MAX];

// ---------------------------------------------------------------------------
// Prep kernel v2: phase A compacts edge_index (int64/int32 ballot-detected)
// to clamped int2. Phase B computes r = ea@W3^T, warp per edge, lane owns
// k-pair; W3 as 16 packed f32x2 pairs, per-d = splat + fma.rn.f32x2.
// ea streamed in two float4 halves to keep regs ~46 (5 blocks/SM).
// ---------------------------------------------------------------------------
__global__ __launch_bounds__(256) void prep_kernel(
    const void* __restrict__ ei_raw,
    const float* __restrict__ ea,
    const float* __restrict__ att_w,
    int E, int N)
{
    const int lane = threadIdx.x & 31;

    // ---- phase A: index compaction ----
    {
        const unsigned int* w = (const unsigned int*)ei_raw;
        unsigned int hi = w[2 * lane + 1];
        const int is64 = (__ballot_sync(0xFFFFFFFFu, hi == 0u) == 0xFFFFFFFFu);

        const long long* ei64 = (const long long*)ei_raw;
        const int*       ei32 = (const int*)ei_raw;

        int i = blockIdx.x * blockDim.x + threadIdx.x;
        int stride = gridDim.x * blockDim.x;
        for (; i < E; i += stride) {
            int si, di;
            if (is64) { si = (int)ei64[i]; di = (int)ei64[E + i]; }
            else      { si = ei32[i];      di = ei32[E + i]; }
            si = min(max(si, 0), N - 1);
            di = min(max(di, 0), N - 1);
            g_eidx[i] = make_int2(si, di);
        }
    }

    // ---- phase B: r-GEMM ----
    const int warp   = blockIdx.x * (blockDim.x >> 5) + (threadIdx.x >> 5);
    const int nwarps = gridDim.x * (blockDim.x >> 5);
    const int AW     = 2 * HDIM + EDIM;  // 144
    const int k0     = lane * 2;

    // w3p[d] = {W3[k0][d], W3[k0+1][d]} packed
    unsigned long long w3p[16];
#pragma unroll
    for (int q = 0; q < 4; q++) {
        float4 va = *(const float4*)&att_w[k0 * AW + 2 * HDIM + q * 4];
        float4 vb = *(const float4*)&att_w[(k0 + 1) * AW + 2 * HDIM + q * 4];
        PACK2(w3p[q * 4 + 0], va.x, vb.x);
        PACK2(w3p[q * 4 + 1], va.y, vb.y);
        PACK2(w3p[q * 4 + 2], va.z, vb.z);
        PACK2(w3p[q * 4 + 3], va.w, vb.w);
    }

    const float4* EA4 = (const float4*)ea;
    for (int e = warp; e < E; e += nwarps) {
        unsigned long long acc;
        {
            unsigned int z = 0;
            asm("mov.b64 %0, {%1, %1};" : "=l"(acc) : "r"(z));
        }
        // first half: d = 0..7
        {
            float4 a0 = EA4[e * 4 + 0];
            float4 a1 = EA4[e * 4 + 1];
            float av[8] = {a0.x, a0.y, a0.z, a0.w, a1.x, a1.y, a1.z, a1.w};
#pragma unroll
            for (int d = 0; d < 8; d++) {
                unsigned long long as;
                PACK2(as, av[d], av[d]);
                FMA2(acc, as, w3p[d], acc);
            }
        }
        // second half: d = 8..15
        {
            float4 a2 = EA4[e * 4 + 2];
            float4 a3 = EA4[e * 4 + 3];
            float av[8] = {a2.x, a2.y, a2.z, a2.w, a3.x, a3.y, a3.z, a3.w};
#pragma unroll
            for (int d = 0; d < 8; d++) {
                unsigned long long as;
                PACK2(as, av[d], av[d]);
                FMA2(acc, as, w3p[d + 8], acc);
            }
        }
        unsigned int ux, uy;
        UNPACK2(ux, uy, acc);
        g_r2[(size_t)e * 32 + lane] =
            __floats2half2_rn(__uint_as_float(ux), __uint_as_float(uy));
    }
}

// ---------------------------------------------------------------------------
// Node kernel (f32x2): tile of 128 nodes per block, 256 threads, 4x8 tile.
// Accumulators packed along k: acc2[i][jp] = {acc[i][2jp], acc[i][2jp+1]}.
// Per c: 4 b-packs (from float4 smem loads) + 4 a-splats + 16 fma.rn.f32x2.
// ---------------------------------------------------------------------------
__global__ __launch_bounds__(256) void node_kernel(
    const float* __restrict__ x,
    const float* __restrict__ fc_w,
    const float* __restrict__ fc_b,
    const float* __restrict__ att_w,
    const float* __restrict__ att_b,
    float* __restrict__ out,
    int N)
{
    __shared__ float hT[64 * 132];
    __shared__ float a_sm[16 * 132];
    __shared__ float b_sm[16 * 68];

    const int t     = threadIdx.x;
    const int tn    = t & 31;
    const int tk    = t >> 5;
    const int kb    = tk * 8;
    const int node0 = blockIdx.x * 128;

    unsigned long long acc2[4][4];

    // ---------------- Stage 1: h ----------------
    {
        unsigned long long bias2[4];
#pragma unroll
        for (int jp = 0; jp < 4; jp++) {
            float b0 = __ldg(&fc_b[kb + 2 * jp]);
            float b1 = __ldg(&fc_b[kb + 2 * jp + 1]);
            PACK2(bias2[jp], b0, b1);
        }
#pragma unroll
        for (int i = 0; i < 4; i++)
#pragma unroll
            for (int jp = 0; jp < 4; jp++) acc2[i][jp] = bias2[jp];

        for (int cb = 0; cb < 8; cb++) {
#pragma unroll
            for (int j = 0; j < 8; j++) {
                int idx = t + j * 256;
                int n = idx >> 4, c = idx & 15;
                int gn = node0 + n;
                float v = (gn < N) ? x[gn * CDIM + cb * 16 + c] : 0.0f;
                a_sm[c * 132 + n] = v;
            }
#pragma unroll
            for (int j = 0; j < 4; j++) {
                int idx = t + j * 256;
                int k = idx >> 4, c = idx & 15;
                b_sm[c * 68 + k] = fc_w[k * CDIM + cb * 16 + c];
            }
            __syncthreads();
#pragma unroll
            for (int c = 0; c < 16; c++) {
                float4 av  = *(const float4*)&a_sm[c * 132 + tn * 4];
                float4 bv0 = *(const float4*)&b_sm[c * 68 + kb];
                float4 bv1 = *(const float4*)&b_sm[c * 68 + kb + 4];
                unsigned long long b2[4];
                PACK2(b2[0], bv0.x, bv0.y);
                PACK2(b2[1], bv0.z, bv0.w);
                PACK2(b2[2], bv1.x, bv1.y);
                PACK2(b2[3], bv1.z, bv1.w);
                float aa[4] = {av.x, av.y, av.z, av.w};
#pragma unroll
                for (int i = 0; i < 4; i++) {
                    unsigned long long as;
                    PACK2(as, aa[i], aa[i]);
                    FMA2(acc2[i][0], as, b2[0], acc2[i][0]);
                    FMA2(acc2[i][1], as, b2[1], acc2[i][1]);
                    FMA2(acc2[i][2], as, b2[2], acc2[i][2]);
                    FMA2(acc2[i][3], as, b2[3], acc2[i][3]);
                }
            }
            __syncthreads();
        }

#pragma unroll
        for (int i = 0; i < 4; i++) {
            float av[8];
#pragma unroll
            for (int jp = 0; jp < 4; jp++) {
                unsigned int u0, u1;
                UNPACK2(u0, u1, acc2[i][jp]);
                av[2 * jp]     = __uint_as_float(u0);
                av[2 * jp + 1] = __uint_as_float(u1);
            }
            int gn = node0 + tn * 4 + i;
            if (gn < N) {
                g_h4[gn * 16 + (kb >> 2)]     = make_float4(av[0], av[1], av[2], av[3]);
                g_h4[gn * 16 + (kb >> 2) + 1] = make_float4(av[4], av[5], av[6], av[7]);
                float4 z = make_float4(0.f, 0.f, 0.f, 0.f);
                *(float4*)&out[(size_t)gn * HDIM + kb]     = z;
                *(float4*)&out[(size_t)gn * HDIM + kb + 4] = z;
            }
#pragma unroll
            for (int j = 0; j < 8; j++)
                hT[(kb + j) * 132 + tn * 4 + i] = av[j];
        }
        __syncthreads();
    }

    // ---------------- Stage 2: s (p=0) and t (p=1) ----------------
    for (int p = 0; p < 2; p++) {
        unsigned long long bias2[4];
#pragma unroll
        for (int jp = 0; jp < 4; jp++) {
            float b0 = (p == 0) ? __ldg(&att_b[kb + 2 * jp]) : 0.0f;
            float b1 = (p == 0) ? __ldg(&att_b[kb + 2 * jp + 1]) : 0.0f;
            PACK2(bias2[jp], b0, b1);
        }
#pragma unroll
        for (int i = 0; i < 4; i++)
#pragma unroll
            for (int jp = 0; jp < 4; jp++) acc2[i][jp] = bias2[jp];

        for (int cb = 0; cb < 4; cb++) {
#pragma unroll
            for (int j = 0; j < 4; j++) {
                int idx = t + j * 256;
                int k = idx >> 4, c = idx & 15;
                b_sm[c * 68 + k] = att_w[k * (2 * HDIM + EDIM) + p * 64 + cb * 16 + c];
            }
            __syncthreads();
#pragma unroll
            for (int c16 = 0; c16 < 16; c16++) {
                int c = cb * 16 + c16;
                float4 av  = *(const float4*)&hT[c * 132 + tn * 4];
                float4 bv0 = *(const float4*)&b_sm[c16 * 68 + kb];
                float4 bv1 = *(const float4*)&b_sm[c16 * 68 + kb + 4];
                unsigned long long b2[4];
                PACK2(b2[0], bv0.x, bv0.y);
                PACK2(b2[1], bv0.z, bv0.w);
                PACK2(b2[2], bv1.x, bv1.y);
                PACK2(b2[3], bv1.z, bv1.w);
                float aa[4] = {av.x, av.y, av.z, av.w};
#pragma unroll
                for (int i = 0; i < 4; i++) {
                    unsigned long long as;
                    PACK2(as, aa[i], aa[i]);
                    FMA2(acc2[i][0], as, b2[0], acc2[i][0]);
                    FMA2(acc2[i][1], as, b2[1], acc2[i][1]);
                    FMA2(acc2[i][2], as, b2[2], acc2[i][2]);
                    FMA2(acc2[i][3], as, b2[3], acc2[i][3]);
                }
            }
            __syncthreads();
        }

        float4* dst = (p == 0) ? g_s4 : g_t4;
#pragma unroll
        for (int i = 0; i < 4; i++) {
            int gn = node0 + tn * 4 + i;
            if (gn < N) {
                float av[8];
#pragma unroll
                for (int jp = 0; jp < 4; jp++) {
                    unsigned int u0, u1;
                    UNPACK2(u0, u1, acc2[i][jp]);
                    av[2 * jp]     = __uint_as_float(u0);
                    av[2 * jp + 1] = __uint_as_float(u1);
                }
                dst[gn * 16 + (kb >> 2)]     = make_float4(av[0], av[1], av[2], av[3]);
                dst[gn * 16 + (kb >> 2) + 1] = make_float4(av[4], av[5], av[6], av[7]);
            }
        }
    }
}

// ---------------------------------------------------------------------------
// Edge kernel v3.1 (unchanged): warp = 2 edges, half-warp per edge, lane owns
// k-quad. 3 gather LDG.128 (s,t,h) + 1 LDG.64 (fp16 r) + leaky + mul +
// 1 red.global.add.v4.f32. ~30 regs -> ~full occupancy.
// ---------------------------------------------------------------------------
__global__ __launch_bounds__(256) void edge_kernel(
    float* __restrict__ out,
    int E)
{
    const int lane = threadIdx.x & 31;
    const int eh   = lane >> 4;
    const int q    = lane & 15;
    const int warp = blockIdx.x * (blockDim.x >> 5) + (threadIdx.x >> 5);
    const int nw   = gridDim.x * (blockDim.x >> 5);

    const uint2* R64 = (const uint2*)g_r2;

    for (int e2 = warp * 2; e2 < E; e2 += nw * 2) {
        int e = e2 + eh;
        if (e >= E) continue;

        int2 p = g_eidx[e];

        float4 s4 = g_s4[p.x * 16 + q];
        float4 t4 = g_t4[p.y * 16 + q];
        float4 h4 = g_h4[p.y * 16 + q];
        uint2 rr  = R64[(size_t)e * 16 + q];
        float2 r01 = __half22float2(*reinterpret_cast<const __half2*>(&rr.x));
        float2 r23 = __half22float2(*reinterpret_cast<const __half2*>(&rr.y));

        float ax = s4.x + t4.x + r01.x;
        float ay = s4.y + t4.y + r01.y;
        float az = s4.z + t4.z + r23.x;
        float aw = s4.w + t4.w + r23.y;
        ax = (ax > 0.0f) ? ax : 0.2f * ax;
        ay = (ay > 0.0f) ? ay : 0.2f * ay;
        az = (az > 0.0f) ? az : 0.2f * az;
        aw = (aw > 0.0f) ? aw : 0.2f * aw;

        float mx = h4.x * ax;
        float my = h4.y * ay;
        float mz = h4.z * az;
        float mw = h4.w * aw;

        float* addr = out + (size_t)p.x * HDIM + q * 4;
        asm volatile("red.global.add.v4.f32 [%0], {%1, %2, %3, %4};"
                     :: "l"(addr), "f"(mx), "f"(my), "f"(mz), "f"(mw)
                     : "memory");
    }
}

extern "C" void kernel_launch(void* const* d_in, const int* in_sizes, int n_in,
                              void* d_out, int out_size)
{
    // Resolve inputs by unique element count (robust to metadata ordering).
    const float* x = 0; const void* ei = 0; const float* ea = 0;
    const float* fc_w = 0; const float* fc_b = 0;
    const float* att_w = 0; const float* att_b = 0;

    int big[3] = {-1, -1, -1};
    for (int i = 0; i < n_in; i++) {
        long long s = in_sizes[i];
        if (s == 64 * 128)      { if (!fc_w) fc_w = (const float*)d_in[i]; }
        else if (s == 64 * 144) { if (!att_w) att_w = (const float*)d_in[i]; }
        else if (s == 64) {
            if (!fc_b) fc_b = (const float*)d_in[i];
            else if (!att_b) att_b = (const float*)d_in[i];
        } else {
            if (big[0] < 0) big[0] = i;
            else if (big[1] < 0) big[1] = i;
            else big[2] = i;
        }
    }
    for (int a = 0; a < 3; a++)
        for (int b = a + 1; b < 3; b++)
            if (in_sizes[big[b]] > in_sizes[big[a]]) { int tmp = big[a]; big[a] = big[b]; big[b] = tmp; }
    ea = (const float*)d_in[big[0]];
    x  = (const float*)d_in[big[1]];
    ei = d_in[big[2]];

    const int N = in_sizes[big[1]] / CDIM;   // 50000
    int E = in_sizes[big[2]] / 2;            // 800000
    if (E > E_MAX) E = E_MAX;
    float* out = (float*)d_out;

    prep_kernel<<<1184, 256>>>(ei, ea, att_w, E, N);
    int tiles = (N + 127) / 128;
    node_kernel<<<tiles, 256>>>(x, fc_w, fc_b, att_w, att_b, out, N);
    edge_kernel<<<1184, 256>>>(out, E);
}

// round 13
// speedup vs baseline: 1.1859x; 1.1859x over previous
#include <cuda_runtime.h>
#include <cuda_fp16.h>

#define CDIM 128
#define HDIM 64
#define EDIM 16
#define N_MAX 50000
#define E_MAX 810000

// Node-level precompute (float4 layout, 16 float4 per node row):
//  g_s4[n*16+q] = (h@W1^T + att_b)[n][4q..4q+3]
//  g_t4[n*16+q] = (h@W2^T)[n][4q..4q+3]
//  g_h4[n*16+q] = (x@fc_w^T + fc_b)[n][4q..4q+3]
// Edge-level precompute:
//  g_r2[e*32+p] = half2{r[2p], r[2p+1]}  (== half[e][64] in k order)
//  g_eidx[e]    = {src, dst} int32, clamped to [0,N)
__device__ float4  g_s4[N_MAX * 16];
__device__ float4  g_t4[N_MAX * 16];
__device__ float4  g_h4[N_MAX * 16];
__device__ __half2 g_r2[(size_t)E_MAX * 32];
__device__ int2    g_eidx[E_MAX];

// ---------------------------------------------------------------------------
// Fused prep+node kernel. Blocks [0, tiles) run the node path (128-node tile,
// 4x8 thread tile, scalar FFMA — the proven R9 schedule). Blocks [tiles, ..)
// run the edge-preprocessing path: index compaction (1 elem/thread) plus a
// block-tiled r-GEMM (128 edges/block, same 4x8 schedule as node stage 1)
// with smem-staged fp16 output for coalesced stores. The two paths are fully
// independent; only the later edge_kernel launch consumes their outputs.
// ---------------------------------------------------------------------------
__global__ __launch_bounds__(256) void fused_kernel(
    const float* __restrict__ x,
    const float* __restrict__ fc_w,
    const float* __restrict__ fc_b,
    const float* __restrict__ att_w,
    const float* __restrict__ att_b,
    const void* __restrict__ ei_raw,
    const float* __restrict__ ea,
    float* __restrict__ out,
    int N, int E, int tiles)
{
    __shared__ float hT[64 * 132];     // node: h transposed / rgemm: fp16 stage
    __shared__ float a_sm[16 * 132];
    __shared__ float b_sm[16 * 68];

    const int t  = threadIdx.x;
    const int tn = t & 31;
    const int tk = t >> 5;
    const int kb = tk * 8;
    const int bx = blockIdx.x;

    if (bx < tiles) {
        // =================== NODE PATH ===================
        const int node0 = bx * 128;
        float acc[4][8];

        // ---------------- Stage 1: h ----------------
        {
            float bias[8];
#pragma unroll
            for (int j = 0; j < 8; j++) bias[j] = __ldg(&fc_b[kb + j]);
#pragma unroll
            for (int i = 0; i < 4; i++)
#pragma unroll
                for (int j = 0; j < 8; j++) acc[i][j] = bias[j];

            for (int cb = 0; cb < 8; cb++) {
#pragma unroll
                for (int j = 0; j < 8; j++) {
                    int idx = t + j * 256;
                    int n = idx >> 4, c = idx & 15;
                    int gn = node0 + n;
                    float v = (gn < N) ? x[gn * CDIM + cb * 16 + c] : 0.0f;
                    a_sm[c * 132 + n] = v;
                }
#pragma unroll
                for (int j = 0; j < 4; j++) {
                    int idx = t + j * 256;
                    int k = idx >> 4, c = idx & 15;
                    b_sm[c * 68 + k] = fc_w[k * CDIM + cb * 16 + c];
                }
                __syncthreads();
#pragma unroll
                for (int c = 0; c < 16; c++) {
                    float4 av  = *(const float4*)&a_sm[c * 132 + tn * 4];
                    float4 bv0 = *(const float4*)&b_sm[c * 68 + kb];
                    float4 bv1 = *(const float4*)&b_sm[c * 68 + kb + 4];
                    float aa[4] = {av.x, av.y, av.z, av.w};
                    float bb[8] = {bv0.x, bv0.y, bv0.z, bv0.w,
                                   bv1.x, bv1.y, bv1.z, bv1.w};
#pragma unroll
                    for (int i = 0; i < 4; i++)
#pragma unroll
                        for (int j = 0; j < 8; j++)
                            acc[i][j] = fmaf(aa[i], bb[j], acc[i][j]);
                }
                __syncthreads();
            }

#pragma unroll
            for (int i = 0; i < 4; i++) {
                int gn = node0 + tn * 4 + i;
                if (gn < N) {
                    float4 v0 = make_float4(acc[i][0], acc[i][1], acc[i][2], acc[i][3]);
                    float4 v1 = make_float4(acc[i][4], acc[i][5], acc[i][6], acc[i][7]);
                    g_h4[gn * 16 + (kb >> 2)]     = v0;
                    g_h4[gn * 16 + (kb >> 2) + 1] = v1;
                    float4 z = make_float4(0.f, 0.f, 0.f, 0.f);
                    *(float4*)&out[(size_t)gn * HDIM + kb]     = z;
                    *(float4*)&out[(size_t)gn * HDIM + kb + 4] = z;
                }
#pragma unroll
                for (int j = 0; j < 8; j++)
                    hT[(kb + j) * 132 + tn * 4 + i] = acc[i][j];
            }
            __syncthreads();
        }

        // ---------------- Stage 2: s (p=0) and t (p=1) ----------------
        for (int p = 0; p < 2; p++) {
            float bias[8];
#pragma unroll
            for (int j = 0; j < 8; j++)
                bias[j] = (p == 0) ? __ldg(&att_b[kb + j]) : 0.0f;
            float acc2[4][8];
#pragma unroll
            for (int i = 0; i < 4; i++)
#pragma unroll
                for (int j = 0; j < 8; j++) acc2[i][j] = bias[j];

            for (int cb = 0; cb < 4; cb++) {
#pragma unroll
                for (int j = 0; j < 4; j++) {
                    int idx = t + j * 256;
                    int k = idx >> 4, c = idx & 15;
                    b_sm[c * 68 + k] = att_w[k * (2 * HDIM + EDIM) + p * 64 + cb * 16 + c];
                }
                __syncthreads();
#pragma unroll
                for (int c16 = 0; c16 < 16; c16++) {
                    int c = cb * 16 + c16;
                    float4 av  = *(const float4*)&hT[c * 132 + tn * 4];
                    float4 bv0 = *(const float4*)&b_sm[c16 * 68 + kb];
                    float4 bv1 = *(const float4*)&b_sm[c16 * 68 + kb + 4];
                    float aa[4] = {av.x, av.y, av.z, av.w};
                    float bb[8] = {bv0.x, bv0.y, bv0.z, bv0.w,
                                   bv1.x, bv1.y, bv1.z, bv1.w};
#pragma unroll
                    for (int i = 0; i < 4; i++)
#pragma unroll
                        for (int j = 0; j < 8; j++)
                            acc2[i][j] = fmaf(aa[i], bb[j], acc2[i][j]);
                }
                __syncthreads();
            }

            float4* dst = (p == 0) ? g_s4 : g_t4;
#pragma unroll
            for (int i = 0; i < 4; i++) {
                int gn = node0 + tn * 4 + i;
                if (gn < N) {
                    float4 v0 = make_float4(acc2[i][0], acc2[i][1], acc2[i][2], acc2[i][3]);
                    float4 v1 = make_float4(acc2[i][4], acc2[i][5], acc2[i][6], acc2[i][7]);
                    dst[gn * 16 + (kb >> 2)]     = v0;
                    dst[gn * 16 + (kb >> 2) + 1] = v1;
                }
            }
        }
    } else {
        // =================== EDGE-PREP PATH ===================
        const int rb = bx - tiles;          // rgemm block index
        const int e0 = rb * 128;            // first edge of this tile

        // ---- index compaction: one element per thread ----
        {
            const unsigned int* w = (const unsigned int*)ei_raw;
            unsigned int hi = w[2 * (t & 31) + 1];
            const int is64 = (__ballot_sync(0xFFFFFFFFu, hi == 0u) == 0xFFFFFFFFu);

            const long long* ei64 = (const long long*)ei_raw;
            const int*       ei32 = (const int*)ei_raw;

            int i = rb * 256 + t;
            if (i < E) {
                int si, di;
                if (is64) { si = (int)ei64[i]; di = (int)ei64[E + i]; }
                else      { si = ei32[i];      di = ei32[E + i]; }
                si = min(max(si, 0), N - 1);
                di = min(max(di, 0), N - 1);
                g_eidx[i] = make_int2(si, di);
            }
        }

        // ---- tiled r-GEMM: r[e][k] = sum_d ea[e][d] * W3[k][d] ----
        // A = ea[e0..e0+127][0..15] transposed into a_sm[d][n]
#pragma unroll
        for (int j = 0; j < 8; j++) {
            int idx = t + j * 256;
            int n = idx >> 4, c = idx & 15;
            int e = e0 + n;
            float v = (e < E) ? ea[e * EDIM + c] : 0.0f;
            a_sm[c * 132 + n] = v;
        }
        // B = W3[k][d] transposed into b_sm[d][k]
#pragma unroll
        for (int j = 0; j < 4; j++) {
            int idx = t + j * 256;
            int k = idx >> 4, c = idx & 15;
            b_sm[c * 68 + k] = att_w[k * (2 * HDIM + EDIM) + 2 * HDIM + c];
        }
        __syncthreads();

        float acc[4][8];
#pragma unroll
        for (int i = 0; i < 4; i++)
#pragma unroll
            for (int j = 0; j < 8; j++) acc[i][j] = 0.0f;

#pragma unroll
        for (int c = 0; c < 16; c++) {
            float4 av  = *(const float4*)&a_sm[c * 132 + tn * 4];
            float4 bv0 = *(const float4*)&b_sm[c * 68 + kb];
            float4 bv1 = *(const float4*)&b_sm[c * 68 + kb + 4];
            float aa[4] = {av.x, av.y, av.z, av.w};
            float bb[8] = {bv0.x, bv0.y, bv0.z, bv0.w,
                           bv1.x, bv1.y, bv1.z, bv1.w};
#pragma unroll
            for (int i = 0; i < 4; i++)
#pragma unroll
                for (int j = 0; j < 8; j++)
                    acc[i][j] = fmaf(aa[i], bb[j], acc[i][j]);
        }
        __syncthreads();   // a_sm/b_sm reads done before hT reuse (paranoia)

        // Stage fp16 result in smem (reuse hT), then coalesced copy out.
        uint4* r_sm = (uint4*)hT;   // half[128][64] viewed as uint4[128*8]
#pragma unroll
        for (int i = 0; i < 4; i++) {
            int n = tn * 4 + i;
            __half2 h01 = __floats2half2_rn(acc[i][0], acc[i][1]);
            __half2 h23 = __floats2half2_rn(acc[i][2], acc[i][3]);
            __half2 h45 = __floats2half2_rn(acc[i][4], acc[i][5]);
            __half2 h67 = __floats2half2_rn(acc[i][6], acc[i][7]);
            uint4 u;
            u.x = *(unsigned int*)&h01;
            u.y = *(unsigned int*)&h23;
            u.z = *(unsigned int*)&h45;
            u.w = *(unsigned int*)&h67;
            r_sm[n * 8 + tk] = u;
        }
        __syncthreads();

        uint4* g_r4u = (uint4*)g_r2;
#pragma unroll
        for (int j = 0; j < 4; j++) {
            int idx = t + j * 256;              // 0..1023
            int e = e0 + (idx >> 3);
            if (e < E)
                g_r4u[(size_t)e0 * 8 + idx] = r_sm[idx];
        }
    }
}

// ---------------------------------------------------------------------------
// Edge kernel v3.1 (unchanged): warp = 2 edges, half-warp per edge, lane owns
// k-quad. 3 gather LDG.128 (s,t,h) + 1 LDG.64 (fp16 r) + leaky + mul +
// 1 red.global.add.v4.f32. ~30 regs -> ~full occupancy.
// ---------------------------------------------------------------------------
__global__ __launch_bounds__(256) void edge_kernel(
    float* __restrict__ out,
    int E)
{
    const int lane = threadIdx.x & 31;
    const int eh   = lane >> 4;
    const int q    = lane & 15;
    const int warp = blockIdx.x * (blockDim.x >> 5) + (threadIdx.x >> 5);
    const int nw   = gridDim.x * (blockDim.x >> 5);

    const uint2* R64 = (const uint2*)g_r2;

    for (int e2 = warp * 2; e2 < E; e2 += nw * 2) {
        int e = e2 + eh;
        if (e >= E) continue;

        int2 p = g_eidx[e];

        float4 s4 = g_s4[p.x * 16 + q];
        float4 t4 = g_t4[p.y * 16 + q];
        float4 h4 = g_h4[p.y * 16 + q];
        uint2 rr  = R64[(size_t)e * 16 + q];
        float2 r01 = __half22float2(*reinterpret_cast<const __half2*>(&rr.x));
        float2 r23 = __half22float2(*reinterpret_cast<const __half2*>(&rr.y));

        float ax = s4.x + t4.x + r01.x;
        float ay = s4.y + t4.y + r01.y;
        float az = s4.z + t4.z + r23.x;
        float aw = s4.w + t4.w + r23.y;
        ax = (ax > 0.0f) ? ax : 0.2f * ax;
        ay = (ay > 0.0f) ? ay : 0.2f * ay;
        az = (az > 0.0f) ? az : 0.2f * az;
        aw = (aw > 0.0f) ? aw : 0.2f * aw;

        float mx = h4.x * ax;
        float my = h4.y * ay;
        float mz = h4.z * az;
        float mw = h4.w * aw;

        float* addr = out + (size_t)p.x * HDIM + q * 4;
        asm volatile("red.global.add.v4.f32 [%0], {%1, %2, %3, %4};"
                     :: "l"(addr), "f"(mx), "f"(my), "f"(mz), "f"(mw)
                     : "memory");
    }
}

extern "C" void kernel_launch(void* const* d_in, const int* in_sizes, int n_in,
                              void* d_out, int out_size)
{
    // Resolve inputs by unique element count (robust to metadata ordering).
    const float* x = 0; const void* ei = 0; const float* ea = 0;
    const float* fc_w = 0; const float* fc_b = 0;
    const float* att_w = 0; const float* att_b = 0;

    int big[3] = {-1, -1, -1};
    for (int i = 0; i < n_in; i++) {
        long long s = in_sizes[i];
        if (s == 64 * 128)      { if (!fc_w) fc_w = (const float*)d_in[i]; }
        else if (s == 64 * 144) { if (!att_w) att_w = (const float*)d_in[i]; }
        else if (s == 64) {
            if (!fc_b) fc_b = (const float*)d_in[i];
            else if (!att_b) att_b = (const float*)d_in[i];
        } else {
            if (big[0] < 0) big[0] = i;
            else if (big[1] < 0) big[1] = i;
            else big[2] = i;
        }
    }
    for (int a = 0; a < 3; a++)
        for (int b = a + 1; b < 3; b++)
            if (in_sizes[big[b]] > in_sizes[big[a]]) { int tmp = big[a]; big[a] = big[b]; big[b] = tmp; }
    ea = (const float*)d_in[big[0]];
    x  = (const float*)d_in[big[1]];
    ei = d_in[big[2]];

    const int N = in_sizes[big[1]] / CDIM;   // 50000
    int E = in_sizes[big[2]] / 2;            // 800000
    if (E > E_MAX) E = E_MAX;
    float* out = (float*)d_out;

    const int tiles   = (N + 127) / 128;     // 391
    const int rblocks = (E + 127) / 128;     // 6250
    fused_kernel<<<tiles + rblocks, 256>>>(x, fc_w, fc_b, att_w, att_b,
                                           ei, ea, out, N, E, tiles);
    edge_kernel<<<1184, 256>>>(out, E);
}